// round 1
// baseline (speedup 1.0000x reference)
#include <cuda_runtime.h>
#include <math.h>

#define NB    256
#define NT    256
#define NV    128
#define ND    384
#define NH    6
#define NL    6
#define NHS   64
#define NFF   1536
#define NTOK  (NB*NT)        /* 65536 */
#define NQKV  (3*ND)         /* 1152  */

// ---------------- scratch (device globals; allocation-free) ----------------
__device__ float g_x   [NTOK*(size_t)ND];
__device__ float g_xn  [NTOK*(size_t)ND];
__device__ float g_qkv [NTOK*(size_t)NQKV];
__device__ float g_ff  [NTOK*(size_t)NFF];
__device__ float g_wqkv[NL*(size_t)ND*NQKV];

// ---------------- embedding ----------------
__global__ void __launch_bounds__(128)
k_embed(const int* __restrict__ idx, const float* __restrict__ tok,
        const float* __restrict__ pos, float* __restrict__ x)
{
    int row = blockIdx.x;           // b*T + t
    int t   = row & (NT-1);
    int v   = idx[row];
    const float* te = tok + (size_t)v*ND;
    const float* pe = pos + (size_t)t*ND;
    float* xr = x + (size_t)row*ND;
    for (int d = threadIdx.x; d < ND; d += 128)
        xr[d] = te[d] + pe[d];
}

// ---------------- QKV weight repack: Wp[l][d][j], j = {Q,K,V} x (h*64+k) ---
__global__ void k_repack(const float* __restrict__ Wq, const float* __restrict__ Wk,
                         const float* __restrict__ Wv, float* __restrict__ Wp)
{
    int i = blockIdx.x*blockDim.x + threadIdx.x;
    const int TOT = NL*ND*NQKV;
    if (i >= TOT) return;
    int j = i % NQKV;
    int d = (i / NQKV) % ND;
    int l = i / (NQKV*ND);
    const float* src; int c;
    if (j < ND)          { src = Wq; c = j;        }
    else if (j < 2*ND)   { src = Wk; c = j - ND;   }
    else                 { src = Wv; c = j - 2*ND; }
    int h = c >> 6, k = c & 63;
    Wp[i] = src[((size_t)((l*NH + h)*ND + d) << 6) + k];
}

// ---------------- LayerNorm (row of 384, block=128) ----------------
__global__ void __launch_bounds__(128)
k_ln(const float* __restrict__ x, const float* __restrict__ g,
     const float* __restrict__ bb, float* __restrict__ y)
{
    int row = blockIdx.x;
    const float* xr = x + (size_t)row*ND;
    float* yr = y + (size_t)row*ND;
    int t = threadIdx.x;
    float v0 = xr[t], v1 = xr[t+128], v2 = xr[t+256];
    float s  = v0+v1+v2;
    float ss = v0*v0+v1*v1+v2*v2;
    #pragma unroll
    for (int o=16;o>0;o>>=1){
        s  += __shfl_xor_sync(0xffffffffu, s,  o);
        ss += __shfl_xor_sync(0xffffffffu, ss, o);
    }
    __shared__ float rs[4], rq[4];
    if ((t&31)==0){ rs[t>>5]=s; rq[t>>5]=ss; }
    __syncthreads();
    float tot  = rs[0]+rs[1]+rs[2]+rs[3];
    float totq = rq[0]+rq[1]+rq[2]+rq[3];
    float mean = tot * (1.f/ND);
    float var  = totq * (1.f/ND) - mean*mean;
    float rstd = rsqrtf(var + 1e-5f);
    yr[t]     = (v0-mean)*rstd*g[t]     + bb[t];
    yr[t+128] = (v1-mean)*rstd*g[t+128] + bb[t+128];
    yr[t+256] = (v2-mean)*rstd*g[t+256] + bb[t+256];
}

// ---------------- fp32 GEMM: C[M,N] = A[M,K] @ B[K,N] (+bias)(+res)(relu) ---
// BM=BN=128, BK=8, 256 threads, 8x8 per thread (split 4+4 for conflict-free LDS)
template<int HAS_BIAS,int RES,int RELU>
__global__ void __launch_bounds__(256)
k_gemm(const float* __restrict__ A, const float* __restrict__ B,
       const float* __restrict__ bias, float* __restrict__ C,
       int M, int N, int K)
{
    __shared__ float As[8][128];
    __shared__ float Bs[8][128];
    const int tid  = threadIdx.x;
    const int bm   = blockIdx.y * 128;
    const int bn   = blockIdx.x * 128;
    const int arow = tid >> 1;
    const int acol = (tid & 1) << 2;
    const int brow = tid >> 5;
    const int bcol = (tid & 31) << 2;
    const int tx   = tid & 15;
    const int ty   = tid >> 4;
    const float* Ap = A + (size_t)(bm + arow) * K + acol;
    const float* Bp = B + (size_t)brow * N + bn + bcol;
    float acc[8][8];
    #pragma unroll
    for (int i=0;i<8;i++)
        #pragma unroll
        for (int j=0;j<8;j++) acc[i][j]=0.f;

    for (int k0 = 0; k0 < K; k0 += 8){
        float4 av = *(const float4*)Ap;
        float4 bv = *(const float4*)Bp;
        Ap += 8; Bp += (size_t)8*N;
        As[acol+0][arow]=av.x; As[acol+1][arow]=av.y;
        As[acol+2][arow]=av.z; As[acol+3][arow]=av.w;
        *(float4*)&Bs[brow][bcol] = bv;
        __syncthreads();
        #pragma unroll
        for (int kk=0; kk<8; kk++){
            float a[8], b[8];
            float4 t0 = *(const float4*)&As[kk][ty*4];
            float4 t1 = *(const float4*)&As[kk][64 + ty*4];
            float4 t2 = *(const float4*)&Bs[kk][tx*4];
            float4 t3 = *(const float4*)&Bs[kk][64 + tx*4];
            a[0]=t0.x;a[1]=t0.y;a[2]=t0.z;a[3]=t0.w;
            a[4]=t1.x;a[5]=t1.y;a[6]=t1.z;a[7]=t1.w;
            b[0]=t2.x;b[1]=t2.y;b[2]=t2.z;b[3]=t2.w;
            b[4]=t3.x;b[5]=t3.y;b[6]=t3.z;b[7]=t3.w;
            #pragma unroll
            for (int i=0;i<8;i++)
                #pragma unroll
                for (int j=0;j<8;j++)
                    acc[i][j] += a[i]*b[j];
        }
        __syncthreads();
    }
    #pragma unroll
    for (int i=0;i<8;i++){
        int row = bm + ((i<4) ? (ty*4+i) : (64 + ty*4 + i - 4));
        #pragma unroll
        for (int j=0;j<8;j++){
            int col = bn + ((j<4) ? (tx*4+j) : (64 + tx*4 + j - 4));
            float v = acc[i][j];
            if (HAS_BIAS) v += bias[col];
            size_t cix = (size_t)row * N + col;
            if (RES)  v += C[cix];
            if (RELU) v = fmaxf(v, 0.f);
            C[cix] = v;
        }
    }
}

// ---------------- fused causal flash attention ----------------
// grid: (B*H, 4 q-tiles of 64), block 256. Q/K/V read from packed qkv buffer.
// K tile is XOR-swizzled in smem (bank-conflict control); its buffer is reused
// to hold P between S-compute and PV.
__global__ void __launch_bounds__(256)
k_attn(const float* __restrict__ qkv, float* __restrict__ out)
{
    __shared__ float Qs[64*64];
    __shared__ float Ks[64*64];   // swizzled K, then P
    __shared__ float Vs[64*64];
    const int tid = threadIdx.x;
    const int bh  = blockIdx.x;
    const int qt  = blockIdx.y;
    const int b   = bh / NH, h = bh % NH;
    const float* base = qkv + (size_t)b * NT * NQKV + h * 64;

    // load Q tile (64 x 64)
    for (int i2 = tid; i2 < 64*16; i2 += 256){
        int r = i2 >> 4, sg = i2 & 15;
        float4 qv = *(const float4*)(base + (size_t)(qt*64 + r)*NQKV + sg*4);
        *(float4*)&Qs[r*64 + sg*4] = qv;
    }
    const int rg = tid >> 4;      // row group 0..15 (rows rg*4..+3)
    const int cg = tid & 15;      // col group

    float o[4][4];
    float mrow[4], lrow[4];
    #pragma unroll
    for (int i=0;i<4;i++){
        mrow[i] = -1e30f; lrow[i] = 0.f;
        #pragma unroll
        for (int c=0;c<4;c++) o[i][c] = 0.f;
    }
    const float scale = 0.125f;   // 64^-0.5

    for (int kt = 0; kt <= qt; kt++){
        __syncthreads();          // previous PV reads of Ks/Vs done
        for (int i2 = tid; i2 < 64*16; i2 += 256){
            int r = i2 >> 4, sg = i2 & 15;
            const float* kro = base + ND + (size_t)(kt*64 + r)*NQKV;
            *(float4*)&Ks[r*64 + ((sg ^ (r & 15)) << 2)] = *(const float4*)(kro + sg*4);
            *(float4*)&Vs[r*64 + sg*4]                   = *(const float4*)(kro + ND + sg*4);
        }
        __syncthreads();

        // S = Q K^T, this thread's 4 rows x 4 cols (cols = cg + 16*j)
        float s[4][4];
        #pragma unroll
        for (int i=0;i<4;i++)
            #pragma unroll
            for (int j=0;j<4;j++) s[i][j]=0.f;
        for (int d0 = 0; d0 < 64; d0 += 4){
            float q[4][4], k[4][4];
            #pragma unroll
            for (int i=0;i<4;i++){
                float4 t = *(const float4*)&Qs[(rg*4+i)*64 + d0];
                q[i][0]=t.x;q[i][1]=t.y;q[i][2]=t.z;q[i][3]=t.w;
            }
            #pragma unroll
            for (int j=0;j<4;j++){
                int r = cg + (j<<4);
                float4 t = *(const float4*)&Ks[r*64 + (((d0>>2) ^ (r & 15))<<2)];
                k[j][0]=t.x;k[j][1]=t.y;k[j][2]=t.z;k[j][3]=t.w;
            }
            #pragma unroll
            for (int i=0;i<4;i++)
                #pragma unroll
                for (int j=0;j<4;j++)
                    #pragma unroll
                    for (int dd=0;dd<4;dd++)
                        s[i][j] += q[i][dd]*k[j][dd];
        }
        #pragma unroll
        for (int i=0;i<4;i++)
            #pragma unroll
            for (int j=0;j<4;j++) s[i][j] *= scale;
        if (kt == qt){
            #pragma unroll
            for (int i=0;i<4;i++)
                #pragma unroll
                for (int j=0;j<4;j++){
                    int rr = rg*4+i, cc = cg + (j<<4);
                    if (cc > rr) s[i][j] = -1e30f;
                }
        }
        // online softmax update (stats replicated across 16 cg lanes)
        #pragma unroll
        for (int i=0;i<4;i++){
            float m = fmaxf(fmaxf(s[i][0],s[i][1]), fmaxf(s[i][2],s[i][3]));
            #pragma unroll
            for (int off=8;off>=1;off>>=1)
                m = fmaxf(m, __shfl_xor_sync(0xffffffffu, m, off));
            float mnew = fmaxf(mrow[i], m);
            float corr = __expf(mrow[i] - mnew);
            float rsum = 0.f;
            #pragma unroll
            for (int j=0;j<4;j++){
                s[i][j] = __expf(s[i][j] - mnew);
                rsum += s[i][j];
            }
            #pragma unroll
            for (int off=8;off>=1;off>>=1)
                rsum += __shfl_xor_sync(0xffffffffu, rsum, off);
            lrow[i] = lrow[i]*corr + rsum;
            mrow[i] = mnew;
            #pragma unroll
            for (int c=0;c<4;c++) o[i][c] *= corr;
        }
        __syncthreads();          // everyone done reading Ks
        // write P into Ks (same swizzle, rows = q-rows)
        #pragma unroll
        for (int i=0;i<4;i++)
            #pragma unroll
            for (int j=0;j<4;j++){
                int rr = rg*4+i, cc = cg + (j<<4);
                Ks[rr*64 + (((cc>>2) ^ (rr & 15))<<2) + (cc & 3)] = s[i][j];
            }
        __syncthreads();
        // O += P @ V  (this thread's 4 rows x cols cg*4..+3)
        for (int j0 = 0; j0 < 64; j0 += 4){
            float p[4][4], v[4][4];
            #pragma unroll
            for (int i=0;i<4;i++){
                int rr = rg*4+i;
                float4 t = *(const float4*)&Ks[rr*64 + (((j0>>2) ^ (rr & 15))<<2)];
                p[i][0]=t.x;p[i][1]=t.y;p[i][2]=t.z;p[i][3]=t.w;
            }
            #pragma unroll
            for (int jj=0;jj<4;jj++){
                float4 t = *(const float4*)&Vs[(j0+jj)*64 + cg*4];
                v[jj][0]=t.x;v[jj][1]=t.y;v[jj][2]=t.z;v[jj][3]=t.w;
            }
            #pragma unroll
            for (int i=0;i<4;i++)
                #pragma unroll
                for (int jj=0;jj<4;jj++)
                    #pragma unroll
                    for (int c=0;c<4;c++)
                        o[i][c] += p[i][jj]*v[jj][c];
        }
    }
    // final write: out[b, qrow, h*64 + c] (= attention output into g_xn)
    #pragma unroll
    for (int i=0;i<4;i++){
        float inv = 1.f / lrow[i];
        size_t rowix = ((size_t)b*NT + qt*64 + rg*4 + i) * ND + h*64 + cg*4;
        #pragma unroll
        for (int c=0;c<4;c++)
            out[rowix + c] = o[i][c] * inv;
    }
}

// ---------------- host launch ----------------
extern "C" void kernel_launch(void* const* d_in, const int* in_sizes, int n_in,
                              void* d_out, int out_size)
{
    (void)in_sizes; (void)n_in; (void)out_size;
    const int*   idx   = (const int*)  d_in[0];
    const float* tok   = (const float*)d_in[1];
    const float* pos   = (const float*)d_in[2];
    const float* Wq    = (const float*)d_in[3];
    const float* Wk    = (const float*)d_in[4];
    const float* Wv    = (const float*)d_in[5];
    const float* Wproj = (const float*)d_in[6];
    const float* bproj = (const float*)d_in[7];
    const float* ln1g  = (const float*)d_in[8];
    const float* ln1b  = (const float*)d_in[9];
    const float* ln2g  = (const float*)d_in[10];
    const float* ln2b  = (const float*)d_in[11];
    const float* W1    = (const float*)d_in[12];
    const float* b1    = (const float*)d_in[13];
    const float* W2    = (const float*)d_in[14];
    const float* b2    = (const float*)d_in[15];
    const float* lnfg  = (const float*)d_in[16];
    const float* lnfb  = (const float*)d_in[17];
    const float* Wlm   = (const float*)d_in[18];
    const float* blm   = (const float*)d_in[19];
    float* out = (float*)d_out;

    float *x, *xn, *qkv, *ff, *wqkv;
    cudaGetSymbolAddress((void**)&x,    g_x);
    cudaGetSymbolAddress((void**)&xn,   g_xn);
    cudaGetSymbolAddress((void**)&qkv,  g_qkv);
    cudaGetSymbolAddress((void**)&ff,   g_ff);
    cudaGetSymbolAddress((void**)&wqkv, g_wqkv);

    k_embed<<<NTOK,128>>>(idx, tok, pos, x);
    k_repack<<<(NL*ND*NQKV + 255)/256, 256>>>(Wq, Wk, Wv, wqkv);

    for (int l = 0; l < NL; l++){
        k_ln<<<NTOK,128>>>(x, ln1g + l*ND, ln1b + l*ND, xn);
        k_gemm<0,0,0><<<dim3(NQKV/128, NTOK/128),256>>>(
            xn, wqkv + (size_t)l*ND*NQKV, (const float*)0, qkv, NTOK, NQKV, ND);
        k_attn<<<dim3(NB*NH, 4),256>>>(qkv, xn);
        k_gemm<1,1,0><<<dim3(ND/128, NTOK/128),256>>>(
            xn, Wproj + (size_t)l*ND*ND, bproj + l*ND, x, NTOK, ND, ND);
        k_ln<<<NTOK,128>>>(x, ln2g + l*ND, ln2b + l*ND, xn);
        k_gemm<1,0,1><<<dim3(NFF/128, NTOK/128),256>>>(
            xn, W1 + (size_t)l*ND*NFF, b1 + l*NFF, ff, NTOK, NFF, ND);
        k_gemm<1,1,0><<<dim3(ND/128, NTOK/128),256>>>(
            ff, W2 + (size_t)l*NFF*ND, b2 + l*ND, x, NTOK, ND, NFF);
    }
    k_ln<<<NTOK,128>>>(x, lnfg, lnfb, xn);
    k_gemm<1,0,0><<<dim3(NV/128, NTOK/128),256>>>(
        xn, Wlm, blm, out, NTOK, NV, ND);
}